// round 3
// baseline (speedup 1.0000x reference)
#include <cuda_runtime.h>
#include <math_constants.h>

#define BS 8
#define NQ 1000
#define D 256
#define NROWS (BS * NQ)
#define TOPK 10
#define MAX_PAIRS (NROWS * TOPK)
#define RPB 8     // rows per block in batched GEMV kernels
#define MROWS 10  // rows per block in mask kernel (1000 % 10 == 0)

// ---------------- scratch (no allocations allowed) ----------------
__device__ float g_id[NROWS * D];     // id_token (only active rows valid)
__device__ float g_cur[NROWS * D];    // running max of masked features (active rows only)
__device__ int   g_pairs[MAX_PAIRS * 2];
__device__ int   g_pair_count;
__device__ int   g_flag[NROWS];       // row needs id_token
__device__ int   g_idrows[NROWS];
__device__ int   g_nid;
__device__ int   g_outrows[NROWS];
__device__ int   g_nout;

__global__ void k_reset() {
    const int i = blockIdx.x * 256 + threadIdx.x;
    if (i < NROWS) g_flag[i] = 0;
    if (i == 0) { g_pair_count = 0; g_nid = 0; g_nout = 0; }
}

__device__ __forceinline__ void atomicMaxFloat(float* addr, float v) {
    if (v >= 0.0f) atomicMax((int*)addr, __float_as_int(v));
    else           atomicMin((unsigned int*)addr, __float_as_uint(v));
}

// 8-row batched GEMV step: acc[r] = bias + sum_k X[r][k] * W[k][t]
// Software-pipelined: next 8 weights prefetched while current tile FMAs run.
__device__ __forceinline__ void gemv8(const float (*X)[D], const float* __restrict__ W,
                                      float bias, int t, float acc[RPB]) {
#pragma unroll
    for (int r = 0; r < RPB; r++) acc[r] = bias;
    float wn[8];
#pragma unroll
    for (int i = 0; i < 8; i++) wn[i] = W[i * D + t];
    for (int k0 = 0; k0 < D; k0 += 8) {
        float w[8];
#pragma unroll
        for (int i = 0; i < 8; i++) w[i] = wn[i];
        if (k0 + 8 < D) {
#pragma unroll
            for (int i = 0; i < 8; i++) wn[i] = W[(k0 + 8 + i) * D + t];
        }
#pragma unroll
        for (int r = 0; r < RPB; r++) {
            const float4 a = *((const float4*)&X[r][k0]);
            const float4 b = *((const float4*)&X[r][k0 + 4]);
            acc[r] = fmaf(a.x, w[0], acc[r]);
            acc[r] = fmaf(a.y, w[1], acc[r]);
            acc[r] = fmaf(a.z, w[2], acc[r]);
            acc[r] = fmaf(a.w, w[3], acc[r]);
            acc[r] = fmaf(b.x, w[4], acc[r]);
            acc[r] = fmaf(b.y, w[5], acc[r]);
            acc[r] = fmaf(b.z, w[6], acc[r]);
            acc[r] = fmaf(b.w, w[7], acc[r]);
        }
    }
}

// ---------------- K2: IoU mask + selection + cur-init + base output ----------------
// 10 rows per block; boxes + seeds cached in shared. Per row:
//  - writes attn_mask
//  - selects top-10 candidates (overlap>=0.5) exactly as stable argsort would
//  - m==0 rows: writes final output  out = tgt + relu(b5)*neg  right here
//  - m>0  rows: initializes g_cur and records row in out-list
__global__ __launch_bounds__(256) void k_mask_sel(
    const float* __restrict__ pred, const float* __restrict__ seed,
    const float* __restrict__ tgt,  const float* __restrict__ b5,
    float* __restrict__ out, float* __restrict__ out_mask)
{
    const int base = blockIdx.x * MROWS;
    const int b = base / NQ;
    const int t = threadIdx.x;

    __shared__ float4 s_box[NQ];
    __shared__ float  s_seed[NQ];
    __shared__ int    s_cnt, s_m;
    __shared__ float  sval[256];
    __shared__ int    sidx[256];

    const float rb5 = fmaxf(b5[t], 0.0f);

    for (int j = t; j < NQ; j += 256) {
        s_box[j]  = ((const float4*)pred)[b * NQ + j];
        s_seed[j] = seed[b * NQ + j];
    }
    __syncthreads();

    for (int r = 0; r < MROWS; r++) {
        const int row = base + r;
        const int li  = row - b * NQ;
        if (t == 0) s_cnt = 0;
        __syncthreads();

        const float4 pb = s_box[li];
        const float bx1 = __fsub_rn(pb.x, __fmul_rn(0.5f, pb.z));
        const float by1 = __fsub_rn(pb.y, __fmul_rn(0.5f, pb.w));
        const float bx2 = __fadd_rn(pb.x, __fmul_rn(0.5f, pb.z));
        const float by2 = __fadd_rn(pb.y, __fmul_rn(0.5f, pb.w));
        const float ai  = __fmul_rn(__fsub_rn(bx2, bx1), __fsub_rn(by2, by1));
        const bool negi = (s_seed[li] == 0.0f);

        for (int j = t; j < NQ; j += 256) {
            const float4 q = s_box[j];
            const float qx1 = __fsub_rn(q.x, __fmul_rn(0.5f, q.z));
            const float qy1 = __fsub_rn(q.y, __fmul_rn(0.5f, q.w));
            const float qx2 = __fadd_rn(q.x, __fmul_rn(0.5f, q.z));
            const float qy2 = __fadd_rn(q.y, __fmul_rn(0.5f, q.w));
            const float aj  = __fmul_rn(__fsub_rn(qx2, qx1), __fsub_rn(qy2, qy1));
            const float w = fmaxf(__fsub_rn(fminf(bx2, qx2), fmaxf(bx1, qx1)), 0.0f);
            const float h = fmaxf(__fsub_rn(fminf(by2, qy2), fmaxf(by1, qy1)), 0.0f);
            const float inter = __fmul_rn(w, h);
            const float uni = __fsub_rn(__fadd_rn(ai, aj), inter);
            const float iou = __fdiv_rn(inter, uni);
            const bool attn = (iou >= 0.5f);
            out_mask[(size_t)row * NQ + j] = attn ? 1.0f : 0.0f;
            if (attn && negi && (s_seed[j] != 0.0f)) {
                int p = atomicAdd(&s_cnt, 1);
                if (p < 256) { sval[p] = iou; sidx[p] = j; }
            }
        }
        __syncthreads();

        if (t == 0) {
            int cnt = min(s_cnt, 256);
            int m;
            int sel[TOPK];
            if (cnt <= TOPK) {
                m = cnt;
                for (int q = 0; q < cnt; q++) sel[q] = sidx[q];
            } else {
                m = TOPK;
                for (int rr = 0; rr < TOPK; rr++) {
                    float best = -1.0f; int bj = 0x7fffffff; int bp = -1;
                    for (int p = 0; p < cnt; p++) {
                        float v = sval[p]; int j = sidx[p];
                        if (v > best || (v == best && j < bj)) { best = v; bj = j; bp = p; }
                    }
                    sel[rr] = bj;
                    sval[bp] = -1.0f;
                }
            }
            s_m = m;
            if (m > 0) {
                int pbase = atomicAdd(&g_pair_count, m);
                for (int q = 0; q < m; q++) {
                    g_pairs[2 * (pbase + q)]     = row;
                    g_pairs[2 * (pbase + q) + 1] = sel[q];
                    g_flag[b * NQ + sel[q]] = 1;
                }
                g_flag[row] = 1;
                int op = atomicAdd(&g_nout, 1);
                g_outrows[op] = row;
            }
        }
        __syncthreads();
        const int m = s_m;
        if (m == 0) {
            // final output for this row: tgt + relu(b5) * neg
            const float neg = 1.0f - s_seed[li];
            out[(size_t)row * D + t] = tgt[(size_t)row * D + t] + rb5 * neg;
        } else {
            g_cur[(size_t)row * D + t] = (m < TOPK) ? 0.0f : -CUDART_INF_F;
        }
    }
}

// ---------------- compaction of id-rows ----------------
__global__ void k_compact() {
    const int i = blockIdx.x * 256 + threadIdx.x;
    if (i < NROWS && g_flag[i]) {
        int p = atomicAdd(&g_nid, 1);
        g_idrows[p] = i;
    }
}

// ---------------- K3: id_token = LN(relu(tgt@W1+b1)@W2+b2), active rows ----------------
__global__ __launch_bounds__(256) void k_idtoken(
    const float* __restrict__ tgt,
    const float* __restrict__ W1, const float* __restrict__ b1,
    const float* __restrict__ W2, const float* __restrict__ b2,
    const float* __restrict__ g2, const float* __restrict__ be2)
{
    const int nact = g_nid;
    const int t = threadIdx.x;

    __shared__ __align__(16) float Ts[RPB][D];
    __shared__ __align__(16) float Hs[RPB][D];
    __shared__ float s_mean[RPB], s_rstd[RPB];
    __shared__ int   srow[RPB];

    const float bias1 = b1[t], bias2 = b2[t];
    const float gg = g2[t], bb = be2[t];

    for (int g0 = blockIdx.x * RPB; g0 < nact; g0 += gridDim.x * RPB) {
        const int ng = min(RPB, nact - g0);
        if (t < RPB) srow[t] = g_idrows[g0 + ((t < ng) ? t : 0)];
        __syncthreads();

        for (int e = t; e < RPB * (D / 4); e += 256) {
            const int p = e >> 6, c = e & 63;
            ((float4*)Ts[p])[c] = ((const float4*)(tgt + (size_t)srow[p] * D))[c];
        }
        __syncthreads();

        float acc[RPB];
        gemv8(Ts, W1, bias1, t, acc);
#pragma unroll
        for (int r = 0; r < RPB; r++) Hs[r][t] = fmaxf(acc[r], 0.0f);
        __syncthreads();

        gemv8(Hs, W2, bias2, t, acc);
#pragma unroll
        for (int r = 0; r < RPB; r++) Ts[r][t] = acc[r];
        __syncthreads();

        // per-row mean/var: warp w handles row w
        const int wid = t >> 5, lid = t & 31;
        {
            float s = 0.0f, sq = 0.0f;
            for (int c = lid; c < D; c += 32) { float v = Ts[wid][c]; s += v; sq += v * v; }
#pragma unroll
            for (int off = 16; off > 0; off >>= 1) {
                s  += __shfl_down_sync(0xffffffff, s,  off);
                sq += __shfl_down_sync(0xffffffff, sq, off);
            }
            if (lid == 0) {
                float m = s * (1.0f / D);
                s_mean[wid] = m;
                s_rstd[wid] = rsqrtf(sq * (1.0f / D) - m * m + 1e-5f);
            }
        }
        __syncthreads();

#pragma unroll
        for (int r = 0; r < RPB; r++)
            if (r < ng)
                g_id[(size_t)srow[r] * D + t] = (acc[r] - s_mean[r]) * s_rstd[r] * gg + bb;
        __syncthreads();
    }
}

// ---------------- K4a: sparse neighbor MLP + atomic max ----------------
__global__ __launch_bounds__(256) void k_feat(
    const float* __restrict__ W3, const float* __restrict__ b3,
    const float* __restrict__ W4, const float* __restrict__ b4)
{
    const int npairs = g_pair_count;
    const int t = threadIdx.x;

    __shared__ __align__(16) float Ds[RPB][D];
    __shared__ __align__(16) float Hs[RPB][D];
    __shared__ int srow[RPB], sj[RPB];

    const float bias3 = b3[t], bias4 = b4[t];

    for (int g0 = blockIdx.x * RPB; g0 < npairs; g0 += gridDim.x * RPB) {
        const int ng = min(RPB, npairs - g0);
        if (t < RPB) {
            if (t < ng) {
                srow[t] = g_pairs[2 * (g0 + t)];
                sj[t]   = g_pairs[2 * (g0 + t) + 1];
            } else {
                srow[t] = -1;
            }
        }
        __syncthreads();

        for (int e = t; e < RPB * (D / 4); e += 256) {
            const int p = e >> 6, c = e & 63;
            const int row = srow[p];
            if (row >= 0) {
                const int bb = row / NQ;
                const float4 a  = ((const float4*)(g_id + (size_t)row * D))[c];
                const float4 nb = ((const float4*)(g_id + (size_t)(bb * NQ + sj[p]) * D))[c];
                float4 dv;
                dv.x = a.x - nb.x; dv.y = a.y - nb.y; dv.z = a.z - nb.z; dv.w = a.w - nb.w;
                ((float4*)Ds[p])[c] = dv;
            } else {
                ((float4*)Ds[p])[c] = make_float4(0.f, 0.f, 0.f, 0.f);
            }
        }
        __syncthreads();

        float acc[RPB];
        gemv8(Ds, W3, bias3, t, acc);
#pragma unroll
        for (int r = 0; r < RPB; r++) Hs[r][t] = fmaxf(acc[r], 0.0f);
        __syncthreads();

        gemv8(Hs, W4, bias4, t, acc);
        for (int r = 0; r < ng; r++)
            atomicMaxFloat(&g_cur[(size_t)srow[r] * D + t], acc[r]);
        __syncthreads();
    }
}

// ---------------- K4b: active rows (m>0, neg==1): out = tgt + relu(cur@W5+b5) ----------------
__global__ __launch_bounds__(256) void k_out_gemv(
    const float* __restrict__ tgt,
    const float* __restrict__ W5, const float* __restrict__ b5,
    float* __restrict__ out)
{
    const int nact = g_nout;
    const int t = threadIdx.x;

    __shared__ __align__(16) float Cs[RPB][D];
    __shared__ int srow[RPB];

    const float bias5 = b5[t];

    for (int g0 = blockIdx.x * RPB; g0 < nact; g0 += gridDim.x * RPB) {
        const int ng = min(RPB, nact - g0);
        if (t < RPB) srow[t] = g_outrows[g0 + ((t < ng) ? t : 0)];
        __syncthreads();

        for (int e = t; e < RPB * (D / 4); e += 256) {
            const int p = e >> 6, c = e & 63;
            ((float4*)Cs[p])[c] = ((const float4*)(g_cur + (size_t)srow[p] * D))[c];
        }
        __syncthreads();

        float acc[RPB];
        gemv8(Cs, W5, bias5, t, acc);
#pragma unroll
        for (int r = 0; r < RPB; r++) {
            if (r < ng) {
                const int row = srow[r];
                out[(size_t)row * D + t] = tgt[(size_t)row * D + t] + fmaxf(acc[r], 0.0f);
            }
        }
        __syncthreads();
    }
}

// ---------------- launch ----------------
extern "C" void kernel_launch(void* const* d_in, const int* in_sizes, int n_in,
                              void* d_out, int out_size) {
    const float* tgt  = (const float*)d_in[0];
    const float* seed = (const float*)d_in[1];
    const float* pred = (const float*)d_in[2];
    const float* W1 = (const float*)d_in[3];  const float* b1 = (const float*)d_in[4];
    const float* W2 = (const float*)d_in[5];  const float* b2 = (const float*)d_in[6];
    const float* g2 = (const float*)d_in[7];  const float* be2 = (const float*)d_in[8];
    const float* W3 = (const float*)d_in[9];  const float* b3 = (const float*)d_in[10];
    const float* W4 = (const float*)d_in[11]; const float* b4 = (const float*)d_in[12];
    const float* W5 = (const float*)d_in[13]; const float* b5 = (const float*)d_in[14];

    float* out = (float*)d_out;                 // cur_tgt: 8*1000*256 floats
    float* out_mask = out + (size_t)NROWS * D;  // attn_mask: 8*1000*1000 floats (0/1)

    k_reset<<<(NROWS + 255) / 256, 256>>>();
    k_mask_sel<<<NROWS / MROWS, 256>>>(pred, seed, tgt, b5, out, out_mask);
    k_compact<<<(NROWS + 255) / 256, 256>>>();
    k_idtoken<<<296, 256>>>(tgt, W1, b1, W2, b2, g2, be2);
    k_feat<<<592, 256>>>(W3, b3, W4, b4);
    k_out_gemv<<<296, 256>>>(tgt, W5, b5, out);
}